// round 10
// baseline (speedup 1.0000x reference)
#include <cuda_runtime.h>
#include <cstdint>

typedef unsigned long long u64;

// ---- packed f32x2 math (Blackwell sm_10x; ptxas never auto-generates these) ----
__device__ __forceinline__ u64 f2mul(u64 a, u64 b) {
    u64 d; asm("mul.rn.f32x2 %0, %1, %2;" : "=l"(d) : "l"(a), "l"(b)); return d;
}
__device__ __forceinline__ u64 f2add(u64 a, u64 b) {
    u64 d; asm("add.rn.f32x2 %0, %1, %2;" : "=l"(d) : "l"(a), "l"(b)); return d;
}
__device__ __forceinline__ u64 f2fma(u64 a, u64 b, u64 c) {
    u64 d; asm("fma.rn.f32x2 %0, %1, %2, %3;" : "=l"(d) : "l"(a), "l"(b), "l"(c)); return d;
}
__device__ __forceinline__ u64 dup2(float f) {
    u64 d; asm("mov.b64 %0, {%1, %1};" : "=l"(d) : "f"(f)); return d;
}

// packed constants {v, v}
#define ONE2   0x3F8000003F800000ULL   // {  1.0,   1.0 }
#define KL2    0xC1800000C1800000ULL   // {-16.0, -16.0 }
#define KL3    0xC0800000C0800000ULL   // { -4.0,  -4.0 }

// Scale-carrying MAJ ladder. Level-1 weights pre-scaled by s=1/8, so level-1
// outputs carry k1 = 1/4, level-2 k2 = 1/2, level-3 k3 = 1 (no final mul).
//   out = (A+B+C) + A*B*C*K  with K = -1/k_in^2
__device__ __forceinline__ u64 maj_lvl(u64 A, u64 B, u64 C, u64 K) {
    u64 t = f2mul(B, C);
    u64 u = f2fma(t, K, ONE2);
    u64 s = f2add(B, C);
    return f2fma(A, u, s);
}
// level-1: weights {sW0,sW1} {sW2,Wp=-s*(W0W1W2)}, patches P0..P2, PP=P0P1P2:
//   s*2*maj = sW0P0 + sW1P1 + sW2P2 + Wp*PP   (4 ops, out scale 1/4)
__device__ __forceinline__ u64 lvl1(ulonglong2 wa, ulonglong2 wb,
                                    u64 P0, u64 P1, u64 P2, u64 PP) {
    u64 s = f2mul(wb.x, P2);
    s = f2fma(wa.y, P1, s);
    s = f2fma(wa.x, P0, s);
    return f2fma(wb.y, PP, s);
}

// x: [8,3,64,64]  weight: [64,3,3,3]  out: [8,64,64,64]
// Block = 128 threads = 64 w-lanes x 2 co-slots; each thread: TWO adjacent
// output rows, batch-pair packed in f32x2, FOUR output channels.
// Channel-outer loop with incremental level-3 carry; 85-reg cap ->
// 6 blocks/SM (24 warps), 888-block residency vs 1024-block grid.
// Grid = (32 row-pairs, 4 batch-pairs, 8 co-eighths) = 1024 blocks.
__global__ void __launch_bounds__(128, 6)
sconv_maj_kernel(const float* __restrict__ x,
                 const float* __restrict__ wgt,
                 float* __restrict__ out)
{
    __shared__ float2 sP[3][4][66];     // [ch][imgrow h0-1..h0+2][col+1], batch-interleaved
    __shared__ u64 sW4[8][9][4];        // per (co_local, triple): {sW0,sW1,sW2,-s*W0W1W2} dup'd

    const int tid = threadIdx.x;
    const int h0  = blockIdx.x * 2;      // first output row of the pair
    const int n0  = blockIdx.y * 2;      // batch pair
    const int z   = blockIdx.z;          // co eighth (8 channels)

    // ---- stage input strip (rows h0-1..h0+2, cols -1..64, 3 ch, 2 batches) ----
    #pragma unroll
    for (int it = 0; it < 7; ++it) {
        int idx = tid + it * 128;
        if (idx < 3 * 4 * 66) {
            int c   = idx / 264;
            int rem = idx - c * 264;
            int r   = rem / 66;
            int col = rem - r * 66;
            int hh  = h0 - 1 + r;
            int ww  = col - 1;
            float2 v = make_float2(0.f, 0.f);
            if (hh >= 0 && hh < 64 && ww >= 0 && ww < 64) {
                int off = (c * 64 + hh) * 64 + ww;
                v.x = x[n0 * 12288 + off];
                v.y = x[n0 * 12288 + 12288 + off];
            }
            sP[c][r][col] = v;
        }
    }
    // ---- weight table for this co eighth, pre-scaled by s = 1/8 ----
    if (tid < 72) {
        int col = tid / 9, q = tid % 9;
        const float* wp = wgt + (z * 8 + col) * 27 + q * 3;
        float w0 = wp[0], w1 = wp[1], w2 = wp[2];
        const float s = 0.125f;
        sW4[col][q][0] = dup2(w0 * s);
        sW4[col][q][1] = dup2(w1 * s);
        sW4[col][q][2] = dup2(w2 * s);
        sW4[col][q][3] = dup2(-(w0 * w1 * w2) * s);
    }
    __syncthreads();

    const int w = tid & 63;    // pixel column
    const int g = tid >> 6;    // co slot (0..1)

    const u64* Pb = reinterpret_cast<const u64*>(&sP[0][0][0]);
    const ulonglong2* wv = reinterpret_cast<const ulonglong2*>(&sW4[g][0][0]);

    const int co0 = z * 8 + g;
    const int ob  = ((n0 * 64 + co0) * 64 + h0) * 64 + w;

    // incremental level-3 carries: running sum / product of level-2 outputs
    u64 Sa[4], Pa[4], Sb[4], Pcb[4];

    #pragma unroll
    for (int c = 0; c < 3; ++c) {
        // ---- current channel's 12 patches + 4 row triple-products ----
        u64 P[4][3], PPr[4];
        #pragma unroll
        for (int r = 0; r < 4; ++r) {
            #pragma unroll
            for (int j = 0; j < 3; ++j)
                P[r][j] = Pb[(c * 4 + r) * 66 + w + j];
            PPr[r] = f2mul(f2mul(P[r][0], P[r][1]), P[r][2]);
        }
        #pragma unroll
        for (int cc = 0; cc < 4; ++cc) {
            u64 l1a[3], l1b[3];
            #pragma unroll
            for (int kr = 0; kr < 3; ++kr) {
                const int q = c * 3 + kr;
                ulonglong2 wa = wv[cc * 36 + 2 * q];       // {sW0, sW1}
                ulonglong2 wb = wv[cc * 36 + 2 * q + 1];   // {sW2, -s*W0W1W2}
                l1a[kr] = lvl1(wa, wb, P[kr  ][0], P[kr  ][1], P[kr  ][2], PPr[kr  ]);
                l1b[kr] = lvl1(wa, wb, P[kr+1][0], P[kr+1][1], P[kr+1][2], PPr[kr+1]);
            }
            u64 ma = maj_lvl(l1a[0], l1a[1], l1a[2], KL2);   // level-2, scale 1/2
            u64 mb = maj_lvl(l1b[0], l1b[1], l1b[2], KL2);

            if (c == 0) {
                Sa[cc] = ma; Pa[cc]  = ma;
                Sb[cc] = mb; Pcb[cc] = mb;
            } else if (c == 1) {
                Sa[cc] = f2add(Sa[cc], ma); Pa[cc]  = f2mul(Pa[cc],  ma);
                Sb[cc] = f2add(Sb[cc], mb); Pcb[cc] = f2mul(Pcb[cc], mb);
            } else {
                // level-3 finalize: out = (S + C) + (P*C)*K3   (scale 1 = true maj)
                u64 ra = f2fma(f2mul(Pa[cc],  ma), KL3, f2add(Sa[cc], ma));
                u64 rb = f2fma(f2mul(Pcb[cc], mb), KL3, f2add(Sb[cc], mb));

                float2 fa, fb;
                asm("mov.b64 {%0, %1}, %2;" : "=f"(fa.x), "=f"(fa.y) : "l"(ra));
                asm("mov.b64 {%0, %1}, %2;" : "=f"(fb.x), "=f"(fb.y) : "l"(rb));
                out[ob + cc * 8192]               = fa.x;    // batch n0,   row h0
                out[ob + cc * 8192 + 64]          = fb.x;    // batch n0,   row h0+1
                out[ob + cc * 8192 + 262144]      = fa.y;    // batch n0+1, row h0
                out[ob + cc * 8192 + 262144 + 64] = fb.y;    // batch n0+1, row h0+1
            }
        }
    }
}

extern "C" void kernel_launch(void* const* d_in, const int* in_sizes, int n_in,
                              void* d_out, int out_size)
{
    const float* x   = (const float*)d_in[0];   // [8,3,64,64]
    const float* wgt = (const float*)d_in[1];   // [64,3,3,3]
    float* out = (float*)d_out;                 // [8,64,64,64]

    dim3 grid(32, 4, 8);   // 32 row-pairs x 4 batch-pairs x 8 co-eighths
    sconv_maj_kernel<<<grid, 128>>>(x, wgt, out);
}

// round 11
// speedup vs baseline: 1.0030x; 1.0030x over previous
#include <cuda_runtime.h>
#include <cstdint>

typedef unsigned long long u64;
typedef unsigned int u32;

// ---- packed f32x2 math (Blackwell sm_10x; ptxas never auto-generates these) ----
__device__ __forceinline__ u64 f2mul(u64 a, u64 b) {
    u64 d; asm("mul.rn.f32x2 %0, %1, %2;" : "=l"(d) : "l"(a), "l"(b)); return d;
}
__device__ __forceinline__ u64 f2add(u64 a, u64 b) {
    u64 d; asm("add.rn.f32x2 %0, %1, %2;" : "=l"(d) : "l"(a), "l"(b)); return d;
}
__device__ __forceinline__ u64 f2fma(u64 a, u64 b, u64 c) {
    u64 d; asm("fma.rn.f32x2 %0, %1, %2, %3;" : "=l"(d) : "l"(a), "l"(b), "l"(c)); return d;
}
__device__ __forceinline__ u64 dup2(float f) {
    u64 d; asm("mov.b64 %0, {%1, %1};" : "=l"(d) : "f"(f)); return d;
}
// pinned shared ops for the level-3 carries: volatile so ptxas cannot promote
// them back into registers (that would re-inflate the live set).
__device__ __forceinline__ void sts64v(u32 a, u64 v) {
    asm volatile("st.shared.b64 [%0], %1;" :: "r"(a), "l"(v));
}
__device__ __forceinline__ u64 lds64v(u32 a) {
    u64 d; asm volatile("ld.shared.b64 %0, [%1];" : "=l"(d) : "r"(a)); return d;
}
__device__ __forceinline__ u32 s2u(const void* p) {
    return (u32)__cvta_generic_to_shared(p);
}

// packed constants {v, v}
#define ONE2   0x3F8000003F800000ULL   // {  1.0,   1.0 }
#define KL2    0xC1800000C1800000ULL   // {-16.0, -16.0 }
#define KL3    0xC0800000C0800000ULL   // { -4.0,  -4.0 }

// Scale-carrying MAJ ladder. Level-1 weights pre-scaled by s=1/8, so level-1
// outputs carry k1 = 1/4, level-2 k2 = 1/2, level-3 k3 = 1 (no final mul).
//   out = (A+B+C) + A*B*C*K  with K = -1/k_in^2
__device__ __forceinline__ u64 maj_lvl(u64 A, u64 B, u64 C, u64 K) {
    u64 t = f2mul(B, C);
    u64 u = f2fma(t, K, ONE2);
    u64 s = f2add(B, C);
    return f2fma(A, u, s);
}
// level-1: weights {sW0,sW1} {sW2,Wp=-s*(W0W1W2)}, patches P0..P2, PP=P0P1P2:
//   s*2*maj = sW0P0 + sW1P1 + sW2P2 + Wp*PP   (4 ops, out scale 1/4)
__device__ __forceinline__ u64 lvl1(ulonglong2 wa, ulonglong2 wb,
                                    u64 P0, u64 P1, u64 P2, u64 PP) {
    u64 s = f2mul(wb.x, P2);
    s = f2fma(wa.y, P1, s);
    s = f2fma(wa.x, P0, s);
    return f2fma(wb.y, PP, s);
}

// x: [8,3,64,64]  weight: [64,3,3,3]  out: [8,64,64,64]
// Block = 128 threads = 64 w-lanes x 2 co-slots; each thread: TWO adjacent
// output rows, batch-pair packed in f32x2, FOUR output channels.
// Channel-outer loop; level-3 carries live in SHARED (per-thread private
// columns) -> ~70 regs -> 7 blocks/SM -> the 1024-block grid is ONE wave.
// Grid = (32 row-pairs, 4 batch-pairs, 8 co-eighths) = 1024 blocks.
__global__ void __launch_bounds__(128, 7)
sconv_maj_kernel(const float* __restrict__ x,
                 const float* __restrict__ wgt,
                 float* __restrict__ out)
{
    __shared__ float2 sP[3][4][66];     // [ch][imgrow h0-1..h0+2][col+1], batch-interleaved
    __shared__ u64 sW4[8][9][4];        // per (co_local, triple): {sW0,sW1,sW2,-s*W0W1W2} dup'd
    __shared__ u64 sM2[16][128];        // level-3 carries [cc*4 + {Sa,Pa,Sb,Pb}][tid]

    const int tid = threadIdx.x;
    const int h0  = blockIdx.x * 2;      // first output row of the pair
    const int n0  = blockIdx.y * 2;      // batch pair
    const int z   = blockIdx.z;          // co eighth (8 channels)

    // ---- stage input strip (rows h0-1..h0+2, cols -1..64, 3 ch, 2 batches) ----
    #pragma unroll
    for (int it = 0; it < 7; ++it) {
        int idx = tid + it * 128;
        if (idx < 3 * 4 * 66) {
            int c   = idx / 264;
            int rem = idx - c * 264;
            int r   = rem / 66;
            int col = rem - r * 66;
            int hh  = h0 - 1 + r;
            int ww  = col - 1;
            float2 v = make_float2(0.f, 0.f);
            if (hh >= 0 && hh < 64 && ww >= 0 && ww < 64) {
                int off = (c * 64 + hh) * 64 + ww;
                v.x = x[n0 * 12288 + off];
                v.y = x[n0 * 12288 + 12288 + off];
            }
            sP[c][r][col] = v;
        }
    }
    // ---- weight table for this co eighth, pre-scaled by s = 1/8 ----
    if (tid < 72) {
        int col = tid / 9, q = tid % 9;
        const float* wp = wgt + (z * 8 + col) * 27 + q * 3;
        float w0 = wp[0], w1 = wp[1], w2 = wp[2];
        const float s = 0.125f;
        sW4[col][q][0] = dup2(w0 * s);
        sW4[col][q][1] = dup2(w1 * s);
        sW4[col][q][2] = dup2(w2 * s);
        sW4[col][q][3] = dup2(-(w0 * w1 * w2) * s);
    }
    __syncthreads();

    const int w = tid & 63;    // pixel column
    const int g = tid >> 6;    // co slot (0..1)

    const u64* Pb = reinterpret_cast<const u64*>(&sP[0][0][0]);
    const ulonglong2* wv = reinterpret_cast<const ulonglong2*>(&sW4[g][0][0]);
    const u32 mb = s2u(&sM2[0][0]) + tid * 8;   // + slot*1024

    const int co0 = z * 8 + g;
    const int ob  = ((n0 * 64 + co0) * 64 + h0) * 64 + w;

    #pragma unroll
    for (int c = 0; c < 3; ++c) {
        // ---- current channel's 12 patches + 4 row triple-products ----
        u64 P[4][3], PPr[4];
        #pragma unroll
        for (int r = 0; r < 4; ++r) {
            #pragma unroll
            for (int j = 0; j < 3; ++j)
                P[r][j] = Pb[(c * 4 + r) * 66 + w + j];
            PPr[r] = f2mul(f2mul(P[r][0], P[r][1]), P[r][2]);
        }
        #pragma unroll
        for (int cc = 0; cc < 4; ++cc) {
            u64 l1a[3], l1b[3];
            #pragma unroll
            for (int kr = 0; kr < 3; ++kr) {
                const int q = c * 3 + kr;
                ulonglong2 wa = wv[cc * 36 + 2 * q];       // {sW0, sW1}
                ulonglong2 wb = wv[cc * 36 + 2 * q + 1];   // {sW2, -s*W0W1W2}
                l1a[kr] = lvl1(wa, wb, P[kr  ][0], P[kr  ][1], P[kr  ][2], PPr[kr  ]);
                l1b[kr] = lvl1(wa, wb, P[kr+1][0], P[kr+1][1], P[kr+1][2], PPr[kr+1]);
            }
            u64 ma = maj_lvl(l1a[0], l1a[1], l1a[2], KL2);   // level-2, scale 1/2
            u64 mb2 = maj_lvl(l1b[0], l1b[1], l1b[2], KL2);

            const u32 slot = mb + cc * 4096;   // 4 slots x 1024B per cc
            if (c == 0) {
                // Sa = Pa = ma (one store, read for both at c==1); same for b
                sts64v(slot,          ma);
                sts64v(slot + 2048,   mb2);
            } else if (c == 1) {
                u64 m0a = lds64v(slot);
                u64 m0b = lds64v(slot + 2048);
                sts64v(slot,          f2add(m0a, ma));    // Sa
                sts64v(slot + 1024,   f2mul(m0a, ma));    // Pa
                sts64v(slot + 2048,   f2add(m0b, mb2));   // Sb
                sts64v(slot + 3072,   f2mul(m0b, mb2));   // Pb
            } else {
                u64 Sa = lds64v(slot),        Pa = lds64v(slot + 1024);
                u64 Sb = lds64v(slot + 2048), Pc = lds64v(slot + 3072);
                // level-3 finalize: out = (S + C) + (P*C)*K3  (scale 1 = true maj)
                u64 ra = f2fma(f2mul(Pa, ma),  KL3, f2add(Sa, ma));
                u64 rb = f2fma(f2mul(Pc, mb2), KL3, f2add(Sb, mb2));

                float2 fa, fb;
                asm("mov.b64 {%0, %1}, %2;" : "=f"(fa.x), "=f"(fa.y) : "l"(ra));
                asm("mov.b64 {%0, %1}, %2;" : "=f"(fb.x), "=f"(fb.y) : "l"(rb));
                out[ob + cc * 8192]               = fa.x;    // batch n0,   row h0
                out[ob + cc * 8192 + 64]          = fb.x;    // batch n0,   row h0+1
                out[ob + cc * 8192 + 262144]      = fa.y;    // batch n0+1, row h0
                out[ob + cc * 8192 + 262144 + 64] = fb.y;    // batch n0+1, row h0+1
            }
        }
    }
}

extern "C" void kernel_launch(void* const* d_in, const int* in_sizes, int n_in,
                              void* d_out, int out_size)
{
    const float* x   = (const float*)d_in[0];   // [8,3,64,64]
    const float* wgt = (const float*)d_in[1];   // [64,3,3,3]
    float* out = (float*)d_out;                 // [8,64,64,64]

    dim3 grid(32, 4, 8);   // 32 row-pairs x 4 batch-pairs x 8 co-eighths
    sconv_maj_kernel<<<grid, 128>>>(x, wgt, out);
}